// round 8
// baseline (speedup 1.0000x reference)
#include <cuda_runtime.h>
#include <cuda_fp16.h>
#include <cstdint>

// ---------------------------------------------------------------------------
// GroupAttention (Swin window attention)
// B=32, N=4096 (64x64), C=128, WS=8 -> G=64 windows, S=64 tokens/window
// heads=4, hd=32.
// Round 8: occupancy push. One fused kernel, 1 window/CTA, 256 threads,
// 3 CTAs/SM target: Q lives in registers (C->A frag pass-through), weights
// streamed from global fp16 straight into B-fragments (no W smem), attention
// split into two 16-row halves to halve live registers.
// SMEM = X(17.4K) + K(17.4K) + V(18.4K) = 53KB.
// ---------------------------------------------------------------------------

#define B_    32
#define NTOK  4096
#define C_    128
#define G_    64
#define S_    64

__device__ __half g_wq_h[384 * 128];
__device__ __half g_wp_h[128 * 128];

__device__ __forceinline__ int token_index(int g, int s) {
    return ((g >> 3) << 9) + ((s >> 3) << 6) + ((g & 7) << 3) + (s & 7);
}

__device__ __forceinline__ uint32_t h2u(__half2 h) { return *(uint32_t*)&h; }

__device__ __forceinline__ uint32_t smem_u32(const void* p) {
    uint32_t a;
    asm("{ .reg .u64 t; cvta.to.shared.u64 t, %1; cvt.u32.u64 %0, t; }"
        : "=r"(a) : "l"(p));
    return a;
}

__device__ __forceinline__ void mma_f16(float* c, const uint32_t* a,
                                        const uint32_t* b) {
    asm volatile(
        "mma.sync.aligned.m16n8k16.row.col.f32.f16.f16.f32 "
        "{%0,%1,%2,%3}, {%4,%5,%6,%7}, {%8,%9}, {%0,%1,%2,%3};"
        : "+f"(c[0]), "+f"(c[1]), "+f"(c[2]), "+f"(c[3])
        : "r"(a[0]), "r"(a[1]), "r"(a[2]), "r"(a[3]), "r"(b[0]), "r"(b[1]));
}

__device__ __forceinline__ void ldmx4(uint32_t* r, uint32_t addr) {
    asm volatile(
        "ldmatrix.sync.aligned.m8n8.x4.shared.b16 {%0,%1,%2,%3}, [%4];"
        : "=r"(r[0]), "=r"(r[1]), "=r"(r[2]), "=r"(r[3]) : "r"(addr));
}

// smem strides in halfwords (word stride % 32 == 4 -> conflict-free ldmatrix)
#define LDH 136
#define VLDH 72

#define OFF_X  0                        // Xs/Oh [64][136] : 17408
#define OFF_K  17408                    // Kh    [64][136] : 17408
#define OFF_V  34816                    // Vt   [128][72]  : 18432
#define SMEM_FUSED 53248                // 3 CTAs/SM = 160KB

#define SCALE 0.17677669529663687f

// ---------------------------------------------------------------------------
__global__ void __launch_bounds__(256) cvt_weights(const float* __restrict__ wq,
                                                   const float* __restrict__ wp) {
    int idx = blockIdx.x * 256 + threadIdx.x;    // 16384 float4 slots
    if (idx < 12288) {
        float4 v = ((const float4*)wq)[idx];
        __half2* d = (__half2*)g_wq_h + idx * 2;
        d[0] = __floats2half2_rn(v.x, v.y);
        d[1] = __floats2half2_rn(v.z, v.w);
    } else {
        int j = idx - 12288;
        float4 v = ((const float4*)wp)[j];
        __half2* d = (__half2*)g_wp_h + j * 2;
        d[0] = __floats2half2_rn(v.x, v.y);
        d[1] = __floats2half2_rn(v.z, v.w);
    }
}

// 32x32 warp-tile GEMM step: A (32 rows) from smem via ldmatrix,
// B (32 weight rows) streamed from global fp16. K=128.
__device__ __forceinline__ void gemm32x32(uint32_t xfrag,
                                          const __half* __restrict__ wt,
                                          float c[2][4][4]) {
    #pragma unroll
    for (int mi = 0; mi < 2; mi++)
        #pragma unroll
        for (int nj = 0; nj < 4; nj++)
            #pragma unroll
            for (int q = 0; q < 4; q++) c[mi][nj][q] = 0.f;

    #pragma unroll
    for (int kt = 0; kt < 8; kt++) {
        uint32_t a0[4], a1[4];
        ldmx4(a0, xfrag + kt * 32);
        ldmx4(a1, xfrag + 16 * LDH * 2 + kt * 32);
        #pragma unroll
        for (int nj = 0; nj < 4; nj++) {
            uint32_t bb[2];
            bb[0] = *(const uint32_t*)(wt + nj * 1024 + kt * 16);
            bb[1] = *(const uint32_t*)(wt + nj * 1024 + kt * 16 + 8);
            mma_f16(c[0][nj], a0, bb);
            mma_f16(c[1][nj], a1, bb);
        }
    }
}

// ---------------------------------------------------------------------------
// Fused kernel: one block per window, 256 threads (8 warps), 3 CTAs/SM.
// Warp w: QKV/proj tile rows (w&1)*32 x cols (w>>1)*32;
// attention: head (w>>1), S rows (w&1)*32.
// ---------------------------------------------------------------------------
__global__ void __launch_bounds__(256, 3)
fused_all(const float* __restrict__ x, const float* __restrict__ bp,
          float* __restrict__ out) {
    extern __shared__ char sm[];
    __half* Xs = (__half*)(sm + OFF_X);       // X, then O
    __half* Kh = (__half*)(sm + OFF_K);
    __half* Vt = (__half*)(sm + OFF_V);

    const uint32_t xb = smem_u32(Xs);
    const uint32_t kb = smem_u32(Kh);
    const uint32_t vb = smem_u32(Vt);

    const int tid = threadIdx.x;
    const int wid = tid >> 5, lane = tid & 31;
    const int lr = lane >> 2, lc = lane & 3;
    const int bg = blockIdx.x;
    const int b = bg >> 6, g = bg & 63;

    const int m0 = (wid & 1) * 32;
    const int n0 = (wid >> 1) * 32;           // head * 32 for attention
    const int hh = n0;

    // ldmatrix lane address components
    const int a_row = lane & 15;
    const int a_k8  = (lane >> 4) << 3;
    const int b_row = ((lane >> 4) << 3) + (lane & 7);
    const int b_k8  = ((lane >> 3) & 1) << 3;

    // ---- load x window (gathered), fp32 -> fp16 ----
    #pragma unroll
    for (int it = 0; it < 8; it++) {
        int fidx = tid + it * 256;            // 2048 float4s: 64 rows x 32
        int s = fidx >> 5;
        int c4 = fidx & 31;
        int n = token_index(g, s);
        float4 v = *(const float4*)(x + ((size_t)b * NTOK + n) * C_ + c4 * 4);
        __half2* dst = (__half2*)(Xs + s * LDH + c4 * 4);
        dst[0] = __floats2half2_rn(v.x, v.y);
        dst[1] = __floats2half2_rn(v.z, v.w);
    }
    __syncthreads();                          // (1) X ready

    const uint32_t xfrag = xb + (((m0 + a_row) * LDH) + a_k8) * 2;
    const __half* __restrict__ wqt = g_wq_h + (size_t)(n0 + lr) * C_ + 2 * lc;

    // ---- Q chunk: result kept in registers, repacked as mma A-fragments ----
    uint32_t qa[2][2][4];
    {
        float cq[2][4][4];
        gemm32x32(xfrag, wqt, cq);
        #pragma unroll
        for (int mi = 0; mi < 2; mi++)
            #pragma unroll
            for (int kt = 0; kt < 2; kt++) {
                qa[mi][kt][0] = h2u(__floats2half2_rn(cq[mi][2 * kt][0],
                                                      cq[mi][2 * kt][1]));
                qa[mi][kt][1] = h2u(__floats2half2_rn(cq[mi][2 * kt][2],
                                                      cq[mi][2 * kt][3]));
                qa[mi][kt][2] = h2u(__floats2half2_rn(cq[mi][2 * kt + 1][0],
                                                      cq[mi][2 * kt + 1][1]));
                qa[mi][kt][3] = h2u(__floats2half2_rn(cq[mi][2 * kt + 1][2],
                                                      cq[mi][2 * kt + 1][3]));
            }
    }

    // ---- K chunk -> Kh smem ----
    {
        float ck[2][4][4];
        gemm32x32(xfrag, wqt + 128 * C_, ck);
        #pragma unroll
        for (int mi = 0; mi < 2; mi++)
            #pragma unroll
            for (int nj = 0; nj < 4; nj++) {
                int col = n0 + nj * 8 + 2 * lc;
                int r = m0 + mi * 16 + lr;
                *(__half2*)(Kh + r * LDH + col) =
                    __floats2half2_rn(ck[mi][nj][0], ck[mi][nj][1]);
                *(__half2*)(Kh + (r + 8) * LDH + col) =
                    __floats2half2_rn(ck[mi][nj][2], ck[mi][nj][3]);
            }
    }

    // ---- V chunk -> Vt smem (transposed) ----
    {
        float cv[2][4][4];
        gemm32x32(xfrag, wqt + 256 * C_, cv);
        #pragma unroll
        for (int mi = 0; mi < 2; mi++)
            #pragma unroll
            for (int nj = 0; nj < 4; nj++) {
                int d = n0 + nj * 8 + 2 * lc;
                int s0 = m0 + mi * 16 + lr;
                Vt[d * VLDH + s0]           = __float2half_rn(cv[mi][nj][0]);
                Vt[(d + 1) * VLDH + s0]     = __float2half_rn(cv[mi][nj][1]);
                Vt[d * VLDH + s0 + 8]       = __float2half_rn(cv[mi][nj][2]);
                Vt[(d + 1) * VLDH + s0 + 8] = __float2half_rn(cv[mi][nj][3]);
            }
    }
    __syncthreads();                          // (2) K, Vt ready

    // ---- attention, one 16-row half at a time (register economy) ----
    __half* Oh = Xs;                          // O overwrites this warp's X rows
    #pragma unroll
    for (int mi = 0; mi < 2; mi++) {
        // S = Q K^T for rows [m0+mi*16, +16)
        float sf[8][4];
        #pragma unroll
        for (int nj = 0; nj < 8; nj++)
            #pragma unroll
            for (int q = 0; q < 4; q++) sf[nj][q] = 0.f;

        #pragma unroll
        for (int kt = 0; kt < 2; kt++) {
            #pragma unroll
            for (int np = 0; np < 4; np++) {
                uint32_t bb[4];
                ldmx4(bb, kb + (((np * 16 + b_row) * LDH) +
                                hh + kt * 16 + b_k8) * 2);
                mma_f16(sf[np * 2], qa[mi][kt], bb);
                mma_f16(sf[np * 2 + 1], qa[mi][kt], bb + 2);
            }
        }

        // softmax (rows lr -> c0c1, lr+8 -> c2c3)
        float mlo = -1e30f, mhi = -1e30f;
        #pragma unroll
        for (int nj = 0; nj < 8; nj++) {
            mlo = fmaxf(mlo, fmaxf(sf[nj][0], sf[nj][1]));
            mhi = fmaxf(mhi, fmaxf(sf[nj][2], sf[nj][3]));
        }
        mlo = fmaxf(mlo, __shfl_xor_sync(0xffffffffu, mlo, 1));
        mlo = fmaxf(mlo, __shfl_xor_sync(0xffffffffu, mlo, 2));
        mhi = fmaxf(mhi, __shfl_xor_sync(0xffffffffu, mhi, 1));
        mhi = fmaxf(mhi, __shfl_xor_sync(0xffffffffu, mhi, 2));

        float slo = 0.f, shi = 0.f;
        uint32_t ph[8][2];
        #pragma unroll
        for (int nj = 0; nj < 8; nj++) {
            float e0 = __expf((sf[nj][0] - mlo) * SCALE);
            float e1 = __expf((sf[nj][1] - mlo) * SCALE);
            float e2 = __expf((sf[nj][2] - mhi) * SCALE);
            float e3 = __expf((sf[nj][3] - mhi) * SCALE);
            slo += e0 + e1;
            shi += e2 + e3;
            ph[nj][0] = h2u(__floats2half2_rn(e0, e1));
            ph[nj][1] = h2u(__floats2half2_rn(e2, e3));
        }
        slo += __shfl_xor_sync(0xffffffffu, slo, 1);
        slo += __shfl_xor_sync(0xffffffffu, slo, 2);
        shi += __shfl_xor_sync(0xffffffffu, shi, 1);
        shi += __shfl_xor_sync(0xffffffffu, shi, 2);
        float invlo = 1.f / slo;
        float invhi = 1.f / shi;

        // O = P V
        float o[4][4];
        #pragma unroll
        for (int nj = 0; nj < 4; nj++)
            #pragma unroll
            for (int q = 0; q < 4; q++) o[nj][q] = 0.f;

        #pragma unroll
        for (int kt = 0; kt < 4; kt++) {
            uint32_t a[4];
            a[0] = ph[2 * kt][0];
            a[1] = ph[2 * kt][1];
            a[2] = ph[2 * kt + 1][0];
            a[3] = ph[2 * kt + 1][1];
            #pragma unroll
            for (int np = 0; np < 2; np++) {
                uint32_t bb[4];
                ldmx4(bb, vb + (((hh + np * 16 + b_row) * VLDH) +
                                kt * 16 + b_k8) * 2);
                mma_f16(o[np * 2], a, bb);
                mma_f16(o[np * 2 + 1], a, bb + 2);
            }
        }

        // normalize + store O into Xs (this warp's own rows)
        int r = m0 + mi * 16 + lr;
        #pragma unroll
        for (int nj = 0; nj < 4; nj++) {
            int col = hh + nj * 8 + 2 * lc;
            *(__half2*)(Oh + r * LDH + col) =
                __floats2half2_rn(o[nj][0] * invlo, o[nj][1] * invlo);
            *(__half2*)(Oh + (r + 8) * LDH + col) =
                __floats2half2_rn(o[nj][2] * invhi, o[nj][3] * invhi);
        }
    }
    __syncthreads();                          // (3) O ready (cross-warp cols)

    // ---- proj GEMM: out = O * Wp^T + bias ----
    {
        const __half* __restrict__ wpt = g_wp_h + (size_t)(n0 + lr) * C_ + 2 * lc;
        float c[2][4][4];
        gemm32x32(xfrag, wpt, c);

        #pragma unroll
        for (int mi = 0; mi < 2; mi++) {
            int r = m0 + mi * 16 + lr;
            int n0t = token_index(g, r);
            int n1t = token_index(g, r + 8);
            float* r0 = out + ((size_t)b * NTOK + n0t) * C_;
            float* r1 = out + ((size_t)b * NTOK + n1t) * C_;
            #pragma unroll
            for (int nj = 0; nj < 4; nj++) {
                int col = n0 + nj * 8 + 2 * lc;
                float bx = bp[col], by = bp[col + 1];
                *(float2*)(r0 + col) = make_float2(c[mi][nj][0] + bx,
                                                   c[mi][nj][1] + by);
                *(float2*)(r1 + col) = make_float2(c[mi][nj][2] + bx,
                                                   c[mi][nj][3] + by);
            }
        }
    }
}

// ---------------------------------------------------------------------------
extern "C" void kernel_launch(void* const* d_in, const int* in_sizes, int n_in,
                              void* d_out, int out_size) {
    (void)in_sizes; (void)n_in; (void)out_size;
    const float* x      = (const float*)d_in[0];
    const float* w_qkv  = (const float*)d_in[1];
    const float* w_proj = (const float*)d_in[2];
    const float* b_proj = (const float*)d_in[3];
    float* out = (float*)d_out;

    cudaFuncSetAttribute(fused_all,
                         cudaFuncAttributeMaxDynamicSharedMemorySize, SMEM_FUSED);

    cvt_weights<<<64, 256>>>(w_qkv, w_proj);
    fused_all<<<B_ * G_, 256, SMEM_FUSED>>>(x, b_proj, out);
}

// round 9
// speedup vs baseline: 1.8949x; 1.8949x over previous
#include <cuda_runtime.h>
#include <cuda_fp16.h>
#include <cstdint>

// ---------------------------------------------------------------------------
// GroupAttention (Swin window attention)
// B=32, N=4096 (64x64), C=128, WS=8 -> G=64 windows, S=64 tokens/window
// heads=4, hd=32.
// Round 9: 3 CTAs/SM with W staged in SMEM. One fused kernel, 1 window/CTA,
// 256 threads. Q in registers (C->A passthrough). V stored K-major; PV
// B-fragments via ldmatrix.trans. W loaded in 64-row halves (17.4KB buffer).
// SMEM = X + Whalf + K + V = 4 x 17408 = 69632 B -> 3 CTAs/SM (24 warps).
// ---------------------------------------------------------------------------

#define B_    32
#define NTOK  4096
#define C_    128
#define G_    64
#define S_    64

__device__ __half g_wq_h[384 * 128];
__device__ __half g_wp_h[128 * 128];

__device__ __forceinline__ int token_index(int g, int s) {
    return ((g >> 3) << 9) + ((s >> 3) << 6) + ((g & 7) << 3) + (s & 7);
}

__device__ __forceinline__ uint32_t h2u(__half2 h) { return *(uint32_t*)&h; }

__device__ __forceinline__ uint32_t smem_u32(const void* p) {
    uint32_t a;
    asm("{ .reg .u64 t; cvta.to.shared.u64 t, %1; cvt.u32.u64 %0, t; }"
        : "=r"(a) : "l"(p));
    return a;
}

__device__ __forceinline__ void mma_f16(float* c, const uint32_t* a,
                                        const uint32_t* b) {
    asm volatile(
        "mma.sync.aligned.m16n8k16.row.col.f32.f16.f16.f32 "
        "{%0,%1,%2,%3}, {%4,%5,%6,%7}, {%8,%9}, {%0,%1,%2,%3};"
        : "+f"(c[0]), "+f"(c[1]), "+f"(c[2]), "+f"(c[3])
        : "r"(a[0]), "r"(a[1]), "r"(a[2]), "r"(a[3]), "r"(b[0]), "r"(b[1]));
}

__device__ __forceinline__ void ldmx4(uint32_t* r, uint32_t addr) {
    asm volatile(
        "ldmatrix.sync.aligned.m8n8.x4.shared.b16 {%0,%1,%2,%3}, [%4];"
        : "=r"(r[0]), "=r"(r[1]), "=r"(r[2]), "=r"(r[3]) : "r"(addr));
}

__device__ __forceinline__ void ldmx4t(uint32_t* r, uint32_t addr) {
    asm volatile(
        "ldmatrix.sync.aligned.m8n8.x4.trans.shared.b16 {%0,%1,%2,%3}, [%4];"
        : "=r"(r[0]), "=r"(r[1]), "=r"(r[2]), "=r"(r[3]) : "r"(addr));
}

// row stride in halfwords: 68 words % 32 == 4 -> conflict-free ldmatrix
#define LDH 136

#define OFF_X  0                        // Xs/Oh  [64][136] : 17408
#define OFF_W  17408                    // Whalf  [64][136] : 17408
#define OFF_K  34816                    // Kh     [64][136] : 17408
#define OFF_V  52224                    // Vh     [64][136] : 17408 (K-major)
#define SMEM_FUSED 69632                // x3 CTAs = 204KB/SM

#define SCALE 0.17677669529663687f

// ---------------------------------------------------------------------------
__global__ void __launch_bounds__(256) cvt_weights(const float* __restrict__ wq,
                                                   const float* __restrict__ wp) {
    int idx = blockIdx.x * 256 + threadIdx.x;    // 16384 float4 slots
    if (idx < 12288) {
        float4 v = ((const float4*)wq)[idx];
        __half2* d = (__half2*)g_wq_h + idx * 2;
        d[0] = __floats2half2_rn(v.x, v.y);
        d[1] = __floats2half2_rn(v.z, v.w);
    } else {
        int j = idx - 12288;
        float4 v = ((const float4*)wp)[j];
        __half2* d = (__half2*)g_wp_h + j * 2;
        d[0] = __floats2half2_rn(v.x, v.y);
        d[1] = __floats2half2_rn(v.z, v.w);
    }
}

// ---------------------------------------------------------------------------
// Fused kernel: one block per window, 256 threads (8 warps), 3 CTAs/SM.
// GEMM warp tile 16x32: warp w -> rows (w&3)*16, cols (w>>2)*32 (per W-half).
// Attention: warp w -> 16 S-rows (w&3)*16, heads {w>>2, (w>>2)+2} serially.
// ---------------------------------------------------------------------------
__global__ void __launch_bounds__(256, 3)
fused_all(const float* __restrict__ x, const float* __restrict__ bp,
          float* __restrict__ out) {
    extern __shared__ char sm[];
    __half* Xs = (__half*)(sm + OFF_X);       // X, then O
    __half* Ws = (__half*)(sm + OFF_W);
    __half* Kh = (__half*)(sm + OFF_K);
    __half* Vh = (__half*)(sm + OFF_V);

    const uint32_t xb = smem_u32(Xs);
    const uint32_t wb = smem_u32(Ws);
    const uint32_t kb = smem_u32(Kh);
    const uint32_t vb = smem_u32(Vh);

    const int tid = threadIdx.x;
    const int wid = tid >> 5, lane = tid & 31;
    const int lr = lane >> 2, lc = lane & 3;
    const int bg = blockIdx.x;
    const int b = bg >> 6, g = bg & 63;

    const int mrow = (wid & 3) * 16;
    const int ncol = (wid >> 2) * 32;

    // ldmatrix lane address components
    const int a_row = lane & 15;                        // A frag (non-trans)
    const int a_k8  = (lane >> 4) << 3;
    const int b_row = ((lane >> 4) << 3) + (lane & 7);  // B frag (non-trans)
    const int b_k8  = ((lane >> 3) & 1) << 3;
    const int v_row = (lane & 7) + (((lane >> 3) & 1) << 3);  // B frag (trans)
    const int v_c8  = (lane >> 4) << 3;

    // ---- load x window (gathered), fp32 -> fp16 ----
    #pragma unroll
    for (int it = 0; it < 8; it++) {
        int fidx = tid + it * 256;            // 2048 float4s: 64 rows x 32
        int s = fidx >> 5;
        int c4 = fidx & 31;
        int n = token_index(g, s);
        float4 v = *(const float4*)(x + ((size_t)b * NTOK + n) * C_ + c4 * 4);
        __half2* dst = (__half2*)(Xs + s * LDH + c4 * 4);
        dst[0] = __floats2half2_rn(v.x, v.y);
        dst[1] = __floats2half2_rn(v.z, v.w);
    }
    __syncthreads();                          // X ready

    const uint32_t xfragA = xb + (((mrow + a_row) * LDH) + a_k8) * 2;

    // ---- QKV: 6 half-chunks of 64 output features ----
    uint32_t qa[2][2][4];                     // [head-idx][kt][regs]

    #pragma unroll
    for (int ch = 0; ch < 6; ch++) {
        // fill W half (64 rows x 128 halves)
        #pragma unroll
        for (int it = 0; it < 4; it++) {
            int fidx = tid + it * 256;        // 1024 uint4s
            int r = fidx >> 4;
            int q = fidx & 15;
            uint4 v = *(const uint4*)(g_wq_h + (size_t)(ch * 64 + r) * C_ + q * 8);
            *(uint4*)(Ws + r * LDH + q * 8) = v;
        }
        __syncthreads();                      // W ready

        float c[4][4];
        #pragma unroll
        for (int nj = 0; nj < 4; nj++)
            #pragma unroll
            for (int q = 0; q < 4; q++) c[nj][q] = 0.f;

        #pragma unroll
        for (int kt = 0; kt < 8; kt++) {
            uint32_t a[4];
            ldmx4(a, xfragA + kt * 32);
            #pragma unroll
            for (int np = 0; np < 2; np++) {
                uint32_t bb[4];
                ldmx4(bb, wb + (((ncol + np * 16 + b_row) * LDH) +
                                kt * 16 + b_k8) * 2);
                mma_f16(c[np * 2], a, bb);
                mma_f16(c[np * 2 + 1], a, bb + 2);
            }
        }

        if (ch < 2) {
            // Q: keep in registers as mma A-fragments (head = (wid>>2)+2*ch)
            #pragma unroll
            for (int kt = 0; kt < 2; kt++) {
                qa[ch][kt][0] = h2u(__floats2half2_rn(c[2 * kt][0], c[2 * kt][1]));
                qa[ch][kt][1] = h2u(__floats2half2_rn(c[2 * kt][2], c[2 * kt][3]));
                qa[ch][kt][2] = h2u(__floats2half2_rn(c[2 * kt + 1][0], c[2 * kt + 1][1]));
                qa[ch][kt][3] = h2u(__floats2half2_rn(c[2 * kt + 1][2], c[2 * kt + 1][3]));
            }
        } else if (ch < 4) {
            __half* T = Kh;
            int cbase = (ch - 2) * 64 + ncol;
            #pragma unroll
            for (int nj = 0; nj < 4; nj++) {
                int col = cbase + nj * 8 + 2 * lc;
                *(__half2*)(T + (mrow + lr) * LDH + col) =
                    __floats2half2_rn(c[nj][0], c[nj][1]);
                *(__half2*)(T + (mrow + lr + 8) * LDH + col) =
                    __floats2half2_rn(c[nj][2], c[nj][3]);
            }
        } else {
            __half* T = Vh;                   // K-major, same as K
            int cbase = (ch - 4) * 64 + ncol;
            #pragma unroll
            for (int nj = 0; nj < 4; nj++) {
                int col = cbase + nj * 8 + 2 * lc;
                *(__half2*)(T + (mrow + lr) * LDH + col) =
                    __floats2half2_rn(c[nj][0], c[nj][1]);
                *(__half2*)(T + (mrow + lr + 8) * LDH + col) =
                    __floats2half2_rn(c[nj][2], c[nj][3]);
            }
        }
        __syncthreads();                      // mma reads done -> W reusable
    }

    // ---- prefetch Wp half 0 into Ws (overlaps attention math) ----
    #pragma unroll
    for (int it = 0; it < 4; it++) {
        int fidx = tid + it * 256;
        int r = fidx >> 4;
        int q = fidx & 15;
        uint4 v = *(const uint4*)(g_wp_h + (size_t)r * C_ + q * 8);
        *(uint4*)(Ws + r * LDH + q * 8) = v;
    }

    // ---- attention: 2 heads serially; O overwrites Xs ----
    __half* Oh = Xs;
    #pragma unroll
    for (int hidx = 0; hidx < 2; hidx++) {
        const int hcol = ((wid >> 2) + 2 * hidx) * 32;

        // S = Q K^T : 16 rows x 64 tokens
        float sf[8][4];
        #pragma unroll
        for (int nj = 0; nj < 8; nj++)
            #pragma unroll
            for (int q = 0; q < 4; q++) sf[nj][q] = 0.f;

        #pragma unroll
        for (int kt = 0; kt < 2; kt++) {
            #pragma unroll
            for (int np = 0; np < 4; np++) {
                uint32_t bb[4];
                ldmx4(bb, kb + (((np * 16 + b_row) * LDH) +
                                hcol + kt * 16 + b_k8) * 2);
                mma_f16(sf[np * 2], qa[hidx][kt], bb);
                mma_f16(sf[np * 2 + 1], qa[hidx][kt], bb + 2);
            }
        }

        // softmax (rows lr -> c0c1, lr+8 -> c2c3)
        float mlo = -1e30f, mhi = -1e30f;
        #pragma unroll
        for (int nj = 0; nj < 8; nj++) {
            mlo = fmaxf(mlo, fmaxf(sf[nj][0], sf[nj][1]));
            mhi = fmaxf(mhi, fmaxf(sf[nj][2], sf[nj][3]));
        }
        mlo = fmaxf(mlo, __shfl_xor_sync(0xffffffffu, mlo, 1));
        mlo = fmaxf(mlo, __shfl_xor_sync(0xffffffffu, mlo, 2));
        mhi = fmaxf(mhi, __shfl_xor_sync(0xffffffffu, mhi, 1));
        mhi = fmaxf(mhi, __shfl_xor_sync(0xffffffffu, mhi, 2));

        float slo = 0.f, shi = 0.f;
        uint32_t ph[8][2];
        #pragma unroll
        for (int nj = 0; nj < 8; nj++) {
            float e0 = __expf((sf[nj][0] - mlo) * SCALE);
            float e1 = __expf((sf[nj][1] - mlo) * SCALE);
            float e2 = __expf((sf[nj][2] - mhi) * SCALE);
            float e3 = __expf((sf[nj][3] - mhi) * SCALE);
            slo += e0 + e1;
            shi += e2 + e3;
            ph[nj][0] = h2u(__floats2half2_rn(e0, e1));
            ph[nj][1] = h2u(__floats2half2_rn(e2, e3));
        }
        slo += __shfl_xor_sync(0xffffffffu, slo, 1);
        slo += __shfl_xor_sync(0xffffffffu, slo, 2);
        shi += __shfl_xor_sync(0xffffffffu, shi, 1);
        shi += __shfl_xor_sync(0xffffffffu, shi, 2);
        float invlo = 1.f / slo;
        float invhi = 1.f / shi;

        // O = P V: B-fragments from K-major Vh via ldmatrix.trans
        float o[4][4];
        #pragma unroll
        for (int nj = 0; nj < 4; nj++)
            #pragma unroll
            for (int q = 0; q < 4; q++) o[nj][q] = 0.f;

        #pragma unroll
        for (int kt = 0; kt < 4; kt++) {
            uint32_t a[4];
            a[0] = ph[2 * kt][0];
            a[1] = ph[2 * kt][1];
            a[2] = ph[2 * kt + 1][0];
            a[3] = ph[2 * kt + 1][1];
            #pragma unroll
            for (int np = 0; np < 2; np++) {
                uint32_t bb[4];
                ldmx4t(bb, vb + (((kt * 16 + v_row) * LDH) +
                                 hcol + np * 16 + v_c8) * 2);
                mma_f16(o[np * 2], a, bb);
                mma_f16(o[np * 2 + 1], a, bb + 2);
            }
        }

        // normalize + store O (this warp's 16 rows, this head's 32 cols)
        #pragma unroll
        for (int nj = 0; nj < 4; nj++) {
            int col = hcol + nj * 8 + 2 * lc;
            *(__half2*)(Oh + (mrow + lr) * LDH + col) =
                __floats2half2_rn(o[nj][0] * invlo, o[nj][1] * invlo);
            *(__half2*)(Oh + (mrow + lr + 8) * LDH + col) =
                __floats2half2_rn(o[nj][2] * invhi, o[nj][3] * invhi);
        }
    }
    __syncthreads();                          // O complete; Wp half0 ready

    // ---- proj: 2 half-chunks of 64 output features ----
    #pragma unroll
    for (int pch = 0; pch < 2; pch++) {
        if (pch == 1) {
            __syncthreads();                  // half0 mma reads done
            #pragma unroll
            for (int it = 0; it < 4; it++) {
                int fidx = tid + it * 256;
                int r = fidx >> 4;
                int q = fidx & 15;
                uint4 v = *(const uint4*)(g_wp_h + (size_t)(64 + r) * C_ + q * 8);
                *(uint4*)(Ws + r * LDH + q * 8) = v;
            }
            __syncthreads();
        }

        float c[4][4];
        #pragma unroll
        for (int nj = 0; nj < 4; nj++)
            #pragma unroll
            for (int q = 0; q < 4; q++) c[nj][q] = 0.f;

        #pragma unroll
        for (int kt = 0; kt < 8; kt++) {
            uint32_t a[4];
            ldmx4(a, xfragA + kt * 32);       // O fragments
            #pragma unroll
            for (int np = 0; np < 2; np++) {
                uint32_t bb[4];
                ldmx4(bb, wb + (((ncol + np * 16 + b_row) * LDH) +
                                kt * 16 + b_k8) * 2);
                mma_f16(c[np * 2], a, bb);
                mma_f16(c[np * 2 + 1], a, bb + 2);
            }
        }

        int n0t = token_index(g, mrow + lr);
        int n1t = token_index(g, mrow + lr + 8);
        float* r0 = out + ((size_t)b * NTOK + n0t) * C_;
        float* r1 = out + ((size_t)b * NTOK + n1t) * C_;
        #pragma unroll
        for (int nj = 0; nj < 4; nj++) {
            int col = pch * 64 + ncol + nj * 8 + 2 * lc;
            float bx = bp[col], by = bp[col + 1];
            *(float2*)(r0 + col) = make_float2(c[nj][0] + bx, c[nj][1] + by);
            *(float2*)(r1 + col) = make_float2(c[nj][2] + bx, c[nj][3] + by);
        }
    }
}

// ---------------------------------------------------------------------------
extern "C" void kernel_launch(void* const* d_in, const int* in_sizes, int n_in,
                              void* d_out, int out_size) {
    (void)in_sizes; (void)n_in; (void)out_size;
    const float* x      = (const float*)d_in[0];
    const float* w_qkv  = (const float*)d_in[1];
    const float* w_proj = (const float*)d_in[2];
    const float* b_proj = (const float*)d_in[3];
    float* out = (float*)d_out;

    cudaFuncSetAttribute(fused_all,
                         cudaFuncAttributeMaxDynamicSharedMemorySize, SMEM_FUSED);

    cvt_weights<<<64, 256>>>(w_qkv, w_proj);
    fused_all<<<B_ * G_, 256, SMEM_FUSED>>>(x, b_proj, out);
}

// round 11
// speedup vs baseline: 2.1833x; 1.1522x over previous
#include <cuda_runtime.h>
#include <cuda_fp16.h>
#include <cstdint>

// ---------------------------------------------------------------------------
// GroupAttention (Swin window attention)
// B=32, N=4096 (64x64), C=128, WS=8 -> G=64 windows, S=64 tokens/window
// heads=4, hd=32.
// Round 11: round-10 design with the cp.async indexing bug fixed
// (chunk stride is 8 halves = 16 bytes, not 16 halves).
// 2 CTAs/SM, 32x32 warp tiles, full-width W chunks, single-pass proj,
// Wp prefetched across the attention phase.
// ---------------------------------------------------------------------------

#define B_    32
#define NTOK  4096
#define C_    128
#define G_    64
#define S_    64

__device__ __half g_wq_h[384 * 128];
__device__ __half g_wp_h[128 * 128];

__device__ __forceinline__ int token_index(int g, int s) {
    return ((g >> 3) << 9) + ((s >> 3) << 6) + ((g & 7) << 3) + (s & 7);
}

__device__ __forceinline__ uint32_t h2u(__half2 h) { return *(uint32_t*)&h; }

__device__ __forceinline__ uint32_t smem_u32(const void* p) {
    uint32_t a;
    asm("{ .reg .u64 t; cvta.to.shared.u64 t, %1; cvt.u32.u64 %0, t; }"
        : "=r"(a) : "l"(p));
    return a;
}

__device__ __forceinline__ void mma_f16(float* c, const uint32_t* a,
                                        const uint32_t* b) {
    asm volatile(
        "mma.sync.aligned.m16n8k16.row.col.f32.f16.f16.f32 "
        "{%0,%1,%2,%3}, {%4,%5,%6,%7}, {%8,%9}, {%0,%1,%2,%3};"
        : "+f"(c[0]), "+f"(c[1]), "+f"(c[2]), "+f"(c[3])
        : "r"(a[0]), "r"(a[1]), "r"(a[2]), "r"(a[3]), "r"(b[0]), "r"(b[1]));
}

__device__ __forceinline__ void ldmx4(uint32_t* r, uint32_t addr) {
    asm volatile(
        "ldmatrix.sync.aligned.m8n8.x4.shared.b16 {%0,%1,%2,%3}, [%4];"
        : "=r"(r[0]), "=r"(r[1]), "=r"(r[2]), "=r"(r[3]) : "r"(addr));
}

__device__ __forceinline__ void ldmx4t(uint32_t* r, uint32_t addr) {
    asm volatile(
        "ldmatrix.sync.aligned.m8n8.x4.trans.shared.b16 {%0,%1,%2,%3}, [%4];"
        : "=r"(r[0]), "=r"(r[1]), "=r"(r[2]), "=r"(r[3]) : "r"(addr));
}

__device__ __forceinline__ void cp16(uint32_t dst, const void* src) {
    asm volatile("cp.async.cg.shared.global [%0], [%1], 16;"
                 :: "r"(dst), "l"(src));
}
#define CP_COMMIT() asm volatile("cp.async.commit_group;" ::: "memory")
#define CP_WAIT0()  asm volatile("cp.async.wait_group 0;" ::: "memory")

// row stride in halfwords: 68 words % 32 == 4 -> conflict-free ldmatrix
#define LDH 136

#define OFF_X  0                        // Xs/Oh  [64][136] : 17408
#define OFF_W  17408                    // Ws    [128][136] : 34816
#define OFF_Q  52224                    // Qs     [64][136] : 17408
#define OFF_K  69632                    // Kh     [64][136] : 17408
#define OFF_V  87040                    // Vh     [64][136] : 17408 (K-major)
#define SMEM_FUSED 104448               // x2 CTAs = 209KB/SM

#define SCALE 0.17677669529663687f

// ---------------------------------------------------------------------------
__global__ void __launch_bounds__(256) cvt_weights(const float* __restrict__ wq,
                                                   const float* __restrict__ wp) {
    int idx = blockIdx.x * 256 + threadIdx.x;    // 16384 float4 slots
    if (idx < 12288) {
        float4 v = ((const float4*)wq)[idx];
        __half2* d = (__half2*)g_wq_h + idx * 2;
        d[0] = __floats2half2_rn(v.x, v.y);
        d[1] = __floats2half2_rn(v.z, v.w);
    } else {
        int j = idx - 12288;
        float4 v = ((const float4*)wp)[j];
        __half2* d = (__half2*)g_wp_h + j * 2;
        d[0] = __floats2half2_rn(v.x, v.y);
        d[1] = __floats2half2_rn(v.z, v.w);
    }
}

// ---------------------------------------------------------------------------
// Fused kernel: one block per window, 256 threads (8 warps), 2 CTAs/SM.
// QKV/proj warp tile 32x32: rows (w&1)*32, cols (w>>1)*32 (within 128).
// Attention: warp w -> 16 S-rows (w&3)*16, heads {w>>2, (w>>2)+2} serially.
// ---------------------------------------------------------------------------
__global__ void __launch_bounds__(256, 2)
fused_all(const float* __restrict__ x, const float* __restrict__ bp,
          float* __restrict__ out) {
    extern __shared__ char sm[];
    __half* Xs = (__half*)(sm + OFF_X);       // X, then O
    __half* Ws = (__half*)(sm + OFF_W);
    __half* Qs = (__half*)(sm + OFF_Q);
    __half* Kh = (__half*)(sm + OFF_K);
    __half* Vh = (__half*)(sm + OFF_V);

    const uint32_t xb = smem_u32(Xs);
    const uint32_t wb = smem_u32(Ws);
    const uint32_t qb = smem_u32(Qs);
    const uint32_t kb = smem_u32(Kh);
    const uint32_t vb = smem_u32(Vh);

    const int tid = threadIdx.x;
    const int wid = tid >> 5, lane = tid & 31;
    const int lr = lane >> 2, lc = lane & 3;
    const int bg = blockIdx.x;
    const int b = bg >> 6, g = bg & 63;

    // GEMM warp tile (32x32)
    const int mrow = (wid & 1) * 32;
    const int ncol = (wid >> 1) * 32;
    // attention warp tile (16 rows)
    const int mrowA = (wid & 3) * 16;

    // ldmatrix lane address components
    const int a_row = lane & 15;                        // A frag (non-trans)
    const int a_k8  = (lane >> 4) << 3;
    const int b_row = ((lane >> 4) << 3) + (lane & 7);  // B frag (non-trans)
    const int b_k8  = ((lane >> 3) & 1) << 3;
    const int v_row = (lane & 7) + (((lane >> 3) & 1) << 3);  // B frag (trans)
    const int v_c8  = (lane >> 4) << 3;

    // W fill via cp.async: 128 rows x 16 chunks(16B = 8 halves) = 2048 chunks,
    // 8 per thread. 16 threads per row, chunk offset = (tid&15)*8 HALVES.
    const int wr  = tid >> 4;           // rows: wr, wr+16, ..., wr+112
    const int wc8 = (tid & 15) * 8;     // half offset within row (0..120)

    // ---- issue W chunk 0 fill, then load x window ----
    #pragma unroll
    for (int it = 0; it < 8; it++) {
        int r = wr + it * 16;
        cp16(wb + (r * LDH + wc8) * 2, g_wq_h + (size_t)r * C_ + wc8);
    }
    CP_COMMIT();

    #pragma unroll
    for (int it = 0; it < 8; it++) {
        int fidx = tid + it * 256;            // 2048 float4s: 64 rows x 32
        int s = fidx >> 5;
        int c4 = fidx & 31;
        int n = token_index(g, s);
        float4 v = *(const float4*)(x + ((size_t)b * NTOK + n) * C_ + c4 * 4);
        __half2* dst = (__half2*)(Xs + s * LDH + c4 * 4);
        dst[0] = __floats2half2_rn(v.x, v.y);
        dst[1] = __floats2half2_rn(v.z, v.w);
    }
    CP_WAIT0();
    __syncthreads();                          // X + W0 ready

    const uint32_t xfrag0 = xb + (((mrow + a_row) * LDH) + a_k8) * 2;
    const uint32_t xfrag1 = xfrag0 + 16 * LDH * 2;

    // ---- QKV: 3 full-width chunks (Q, K, V) ----
    #pragma unroll
    for (int ch = 0; ch < 3; ch++) {
        float c[2][4][4];
        #pragma unroll
        for (int mi = 0; mi < 2; mi++)
            #pragma unroll
            for (int nj = 0; nj < 4; nj++)
                #pragma unroll
                for (int q = 0; q < 4; q++) c[mi][nj][q] = 0.f;

        #pragma unroll
        for (int kt = 0; kt < 8; kt++) {
            uint32_t a0[4], a1[4];
            ldmx4(a0, xfrag0 + kt * 32);
            ldmx4(a1, xfrag1 + kt * 32);
            #pragma unroll
            for (int np = 0; np < 2; np++) {
                uint32_t bb[4];
                ldmx4(bb, wb + (((ncol + np * 16 + b_row) * LDH) +
                                kt * 16 + b_k8) * 2);
                mma_f16(c[0][np * 2], a0, bb);
                mma_f16(c[0][np * 2 + 1], a0, bb + 2);
                mma_f16(c[1][np * 2], a1, bb);
                mma_f16(c[1][np * 2 + 1], a1, bb + 2);
            }
        }

        // epilogue: all targets K-major [64][LDH]
        __half* T = (ch == 0) ? Qs : (ch == 1) ? Kh : Vh;
        #pragma unroll
        for (int mi = 0; mi < 2; mi++)
            #pragma unroll
            for (int nj = 0; nj < 4; nj++) {
                int r = mrow + mi * 16 + lr;
                int col = ncol + nj * 8 + 2 * lc;
                *(__half2*)(T + r * LDH + col) =
                    __floats2half2_rn(c[mi][nj][0], c[mi][nj][1]);
                *(__half2*)(T + (r + 8) * LDH + col) =
                    __floats2half2_rn(c[mi][nj][2], c[mi][nj][3]);
            }
        __syncthreads();                      // mma reads + epilogue done

        if (ch < 2) {
            const __half* src = g_wq_h + (size_t)(ch + 1) * 128 * C_;
            #pragma unroll
            for (int it = 0; it < 8; it++) {
                int r = wr + it * 16;
                cp16(wb + (r * LDH + wc8) * 2, src + (size_t)r * C_ + wc8);
            }
            CP_COMMIT();
            CP_WAIT0();
            __syncthreads();                  // next W ready
        }
    }

    // ---- prefetch full Wp (overlaps the attention phase) ----
    #pragma unroll
    for (int it = 0; it < 8; it++) {
        int r = wr + it * 16;
        cp16(wb + (r * LDH + wc8) * 2, g_wp_h + (size_t)r * C_ + wc8);
    }
    CP_COMMIT();

    // ---- attention: 2 heads serially; O overwrites Xs ----
    __half* Oh = Xs;
    #pragma unroll
    for (int hidx = 0; hidx < 2; hidx++) {
        const int hcol = ((wid >> 2) + 2 * hidx) * 32;

        // Q A-fragments for this head (16 rows x 32 k)
        uint32_t qa[2][4];
        #pragma unroll
        for (int kt = 0; kt < 2; kt++)
            ldmx4(qa[kt], qb + (((mrowA + a_row) * LDH) +
                                hcol + kt * 16 + a_k8) * 2);

        // S = Q K^T : 16 rows x 64 tokens
        float sf[8][4];
        #pragma unroll
        for (int nj = 0; nj < 8; nj++)
            #pragma unroll
            for (int q = 0; q < 4; q++) sf[nj][q] = 0.f;

        #pragma unroll
        for (int kt = 0; kt < 2; kt++) {
            #pragma unroll
            for (int np = 0; np < 4; np++) {
                uint32_t bb[4];
                ldmx4(bb, kb + (((np * 16 + b_row) * LDH) +
                                hcol + kt * 16 + b_k8) * 2);
                mma_f16(sf[np * 2], qa[kt], bb);
                mma_f16(sf[np * 2 + 1], qa[kt], bb + 2);
            }
        }

        // softmax (rows lr -> c0c1, lr+8 -> c2c3)
        float mlo = -1e30f, mhi = -1e30f;
        #pragma unroll
        for (int nj = 0; nj < 8; nj++) {
            mlo = fmaxf(mlo, fmaxf(sf[nj][0], sf[nj][1]));
            mhi = fmaxf(mhi, fmaxf(sf[nj][2], sf[nj][3]));
        }
        mlo = fmaxf(mlo, __shfl_xor_sync(0xffffffffu, mlo, 1));
        mlo = fmaxf(mlo, __shfl_xor_sync(0xffffffffu, mlo, 2));
        mhi = fmaxf(mhi, __shfl_xor_sync(0xffffffffu, mhi, 1));
        mhi = fmaxf(mhi, __shfl_xor_sync(0xffffffffu, mhi, 2));

        float slo = 0.f, shi = 0.f;
        uint32_t ph[8][2];
        #pragma unroll
        for (int nj = 0; nj < 8; nj++) {
            float e0 = __expf((sf[nj][0] - mlo) * SCALE);
            float e1 = __expf((sf[nj][1] - mlo) * SCALE);
            float e2 = __expf((sf[nj][2] - mhi) * SCALE);
            float e3 = __expf((sf[nj][3] - mhi) * SCALE);
            slo += e0 + e1;
            shi += e2 + e3;
            ph[nj][0] = h2u(__floats2half2_rn(e0, e1));
            ph[nj][1] = h2u(__floats2half2_rn(e2, e3));
        }
        slo += __shfl_xor_sync(0xffffffffu, slo, 1);
        slo += __shfl_xor_sync(0xffffffffu, slo, 2);
        shi += __shfl_xor_sync(0xffffffffu, shi, 1);
        shi += __shfl_xor_sync(0xffffffffu, shi, 2);
        float invlo = 1.f / slo;
        float invhi = 1.f / shi;

        // O = P V: B-fragments from K-major Vh via ldmatrix.trans
        float o[4][4];
        #pragma unroll
        for (int nj = 0; nj < 4; nj++)
            #pragma unroll
            for (int q = 0; q < 4; q++) o[nj][q] = 0.f;

        #pragma unroll
        for (int kt = 0; kt < 4; kt++) {
            uint32_t a[4];
            a[0] = ph[2 * kt][0];
            a[1] = ph[2 * kt][1];
            a[2] = ph[2 * kt + 1][0];
            a[3] = ph[2 * kt + 1][1];
            #pragma unroll
            for (int np = 0; np < 2; np++) {
                uint32_t bb[4];
                ldmx4t(bb, vb + (((kt * 16 + v_row) * LDH) +
                                 hcol + np * 16 + v_c8) * 2);
                mma_f16(o[np * 2], a, bb);
                mma_f16(o[np * 2 + 1], a, bb + 2);
            }
        }

        // normalize + store O (this warp's 16 rows, this head's 32 cols)
        #pragma unroll
        for (int nj = 0; nj < 4; nj++) {
            int col = hcol + nj * 8 + 2 * lc;
            *(__half2*)(Oh + (mrowA + lr) * LDH + col) =
                __floats2half2_rn(o[nj][0] * invlo, o[nj][1] * invlo);
            *(__half2*)(Oh + (mrowA + lr + 8) * LDH + col) =
                __floats2half2_rn(o[nj][2] * invhi, o[nj][3] * invhi);
        }
    }
    CP_WAIT0();
    __syncthreads();                          // O complete; Wp ready

    // ---- proj: single pass, out = O * Wp^T + bias ----
    {
        float c[2][4][4];
        #pragma unroll
        for (int mi = 0; mi < 2; mi++)
            #pragma unroll
            for (int nj = 0; nj < 4; nj++)
                #pragma unroll
                for (int q = 0; q < 4; q++) c[mi][nj][q] = 0.f;

        #pragma unroll
        for (int kt = 0; kt < 8; kt++) {
            uint32_t a0[4], a1[4];
            ldmx4(a0, xfrag0 + kt * 32);      // O fragments
            ldmx4(a1, xfrag1 + kt * 32);
            #pragma unroll
            for (int np = 0; np < 2; np++) {
                uint32_t bb[4];
                ldmx4(bb, wb + (((ncol + np * 16 + b_row) * LDH) +
                                kt * 16 + b_k8) * 2);
                mma_f16(c[0][np * 2], a0, bb);
                mma_f16(c[0][np * 2 + 1], a0, bb + 2);
                mma_f16(c[1][np * 2], a1, bb);
                mma_f16(c[1][np * 2 + 1], a1, bb + 2);
            }
        }

        #pragma unroll
        for (int mi = 0; mi < 2; mi++) {
            int r = mrow + mi * 16 + lr;
            int n0t = token_index(g, r);
            int n1t = token_index(g, r + 8);
            float* r0 = out + ((size_t)b * NTOK + n0t) * C_;
            float* r1 = out + ((size_t)b * NTOK + n1t) * C_;
            #pragma unroll
            for (int nj = 0; nj < 4; nj++) {
                int col = ncol + nj * 8 + 2 * lc;
                float bx = bp[col], by = bp[col + 1];
                *(float2*)(r0 + col) = make_float2(c[mi][nj][0] + bx,
                                                   c[mi][nj][1] + by);
                *(float2*)(r1 + col) = make_float2(c[mi][nj][2] + bx,
                                                   c[mi][nj][3] + by);
            }
        }
    }
}

// ---------------------------------------------------------------------------
extern "C" void kernel_launch(void* const* d_in, const int* in_sizes, int n_in,
                              void* d_out, int out_size) {
    (void)in_sizes; (void)n_in; (void)out_size;
    const float* x      = (const float*)d_in[0];
    const float* w_qkv  = (const float*)d_in[1];
    const float* w_proj = (const float*)d_in[2];
    const float* b_proj = (const float*)d_in[3];
    float* out = (float*)d_out;

    cudaFuncSetAttribute(fused_all,
                         cudaFuncAttributeMaxDynamicSharedMemorySize, SMEM_FUSED);

    cvt_weights<<<64, 256>>>(w_qkv, w_proj);
    fused_all<<<B_ * G_, 256, SMEM_FUSED>>>(x, b_proj, out);
}

// round 12
// speedup vs baseline: 2.2019x; 1.0085x over previous
#include <cuda_runtime.h>
#include <cuda_fp16.h>
#include <cstdint>

// ---------------------------------------------------------------------------
// GroupAttention (Swin window attention)
// B=32, N=4096 (64x64), C=128, WS=8 -> G=64 windows, S=64 tokens/window
// heads=4, hd=32.
// Round 12: Q stays in registers (C->A repack; attention warp map aligned to
// the GEMM warp map), 32-row single-pass attention sharing K/V fragments
// across both 16-row subtiles. SMEM = X + W + K + V = 87KB, 2 CTAs/SM.
// ---------------------------------------------------------------------------

#define B_    32
#define NTOK  4096
#define C_    128
#define G_    64
#define S_    64

__device__ __half g_wq_h[384 * 128];
__device__ __half g_wp_h[128 * 128];

__device__ __forceinline__ int token_index(int g, int s) {
    return ((g >> 3) << 9) + ((s >> 3) << 6) + ((g & 7) << 3) + (s & 7);
}

__device__ __forceinline__ uint32_t h2u(__half2 h) { return *(uint32_t*)&h; }

__device__ __forceinline__ uint32_t smem_u32(const void* p) {
    uint32_t a;
    asm("{ .reg .u64 t; cvta.to.shared.u64 t, %1; cvt.u32.u64 %0, t; }"
        : "=r"(a) : "l"(p));
    return a;
}

__device__ __forceinline__ void mma_f16(float* c, const uint32_t* a,
                                        const uint32_t* b) {
    asm volatile(
        "mma.sync.aligned.m16n8k16.row.col.f32.f16.f16.f32 "
        "{%0,%1,%2,%3}, {%4,%5,%6,%7}, {%8,%9}, {%0,%1,%2,%3};"
        : "+f"(c[0]), "+f"(c[1]), "+f"(c[2]), "+f"(c[3])
        : "r"(a[0]), "r"(a[1]), "r"(a[2]), "r"(a[3]), "r"(b[0]), "r"(b[1]));
}

__device__ __forceinline__ void ldmx4(uint32_t* r, uint32_t addr) {
    asm volatile(
        "ldmatrix.sync.aligned.m8n8.x4.shared.b16 {%0,%1,%2,%3}, [%4];"
        : "=r"(r[0]), "=r"(r[1]), "=r"(r[2]), "=r"(r[3]) : "r"(addr));
}

__device__ __forceinline__ void ldmx4t(uint32_t* r, uint32_t addr) {
    asm volatile(
        "ldmatrix.sync.aligned.m8n8.x4.trans.shared.b16 {%0,%1,%2,%3}, [%4];"
        : "=r"(r[0]), "=r"(r[1]), "=r"(r[2]), "=r"(r[3]) : "r"(addr));
}

__device__ __forceinline__ void cp16(uint32_t dst, const void* src) {
    asm volatile("cp.async.cg.shared.global [%0], [%1], 16;"
                 :: "r"(dst), "l"(src));
}
#define CP_COMMIT() asm volatile("cp.async.commit_group;" ::: "memory")
#define CP_WAIT0()  asm volatile("cp.async.wait_group 0;" ::: "memory")

// row stride in halfwords: 68 words % 32 == 4 -> conflict-free ldmatrix
#define LDH 136

#define OFF_X  0                        // Xs/Oh  [64][136] : 17408
#define OFF_W  17408                    // Ws    [128][136] : 34816
#define OFF_K  52224                    // Kh     [64][136] : 17408
#define OFF_V  69632                    // Vh     [64][136] : 17408 (K-major)
#define SMEM_FUSED 87040                // x2 CTAs = 174KB/SM

#define SCALE 0.17677669529663687f

// ---------------------------------------------------------------------------
__global__ void __launch_bounds__(256) cvt_weights(const float* __restrict__ wq,
                                                   const float* __restrict__ wp) {
    int idx = blockIdx.x * 256 + threadIdx.x;    // 16384 float4 slots
    if (idx < 12288) {
        float4 v = ((const float4*)wq)[idx];
        __half2* d = (__half2*)g_wq_h + idx * 2;
        d[0] = __floats2half2_rn(v.x, v.y);
        d[1] = __floats2half2_rn(v.z, v.w);
    } else {
        int j = idx - 12288;
        float4 v = ((const float4*)wp)[j];
        __half2* d = (__half2*)g_wp_h + j * 2;
        d[0] = __floats2half2_rn(v.x, v.y);
        d[1] = __floats2half2_rn(v.z, v.w);
    }
}

// ---------------------------------------------------------------------------
// Fused kernel: one block per window, 256 threads (8 warps), 2 CTAs/SM.
// Warp w: GEMM tile rows (w&1)*32 x cols (w>>1)*32.
// Attention: same warp -> S-rows (w&1)*32, head (w>>1) (Q frags in regs).
// ---------------------------------------------------------------------------
__global__ void __launch_bounds__(256, 2)
fused_all(const float* __restrict__ x, const float* __restrict__ bp,
          float* __restrict__ out) {
    extern __shared__ char sm[];
    __half* Xs = (__half*)(sm + OFF_X);       // X, then O
    __half* Ws = (__half*)(sm + OFF_W);
    __half* Kh = (__half*)(sm + OFF_K);
    __half* Vh = (__half*)(sm + OFF_V);

    const uint32_t xb = smem_u32(Xs);
    const uint32_t wb = smem_u32(Ws);
    const uint32_t kb = smem_u32(Kh);
    const uint32_t vb = smem_u32(Vh);

    const int tid = threadIdx.x;
    const int wid = tid >> 5, lane = tid & 31;
    const int lr = lane >> 2, lc = lane & 3;
    const int bg = blockIdx.x;
    const int b = bg >> 6, g = bg & 63;

    // warp tile (rows also = attention rows; cols also = head*32)
    const int mrow = (wid & 1) * 32;
    const int ncol = (wid >> 1) * 32;
    const int hcol = ncol;

    // ldmatrix lane address components
    const int a_row = lane & 15;                        // A frag (non-trans)
    const int a_k8  = (lane >> 4) << 3;
    const int b_row = ((lane >> 4) << 3) + (lane & 7);  // B frag (non-trans)
    const int b_k8  = ((lane >> 3) & 1) << 3;
    const int v_row = (lane & 7) + (((lane >> 3) & 1) << 3);  // B frag (trans)
    const int v_c8  = (lane >> 4) << 3;

    // W fill via cp.async: 128 rows x 16 chunks(16B), 8 chunks/thread
    const int wr  = tid >> 4;           // rows: wr, wr+16, ..., wr+112
    const int wc8 = (tid & 15) * 8;     // half offset within row (0..120)

    // ---- issue W chunk 0 fill, then load x window ----
    #pragma unroll
    for (int it = 0; it < 8; it++) {
        int r = wr + it * 16;
        cp16(wb + (r * LDH + wc8) * 2, g_wq_h + (size_t)r * C_ + wc8);
    }
    CP_COMMIT();

    #pragma unroll
    for (int it = 0; it < 8; it++) {
        int fidx = tid + it * 256;            // 2048 float4s: 64 rows x 32
        int s = fidx >> 5;
        int c4 = fidx & 31;
        int n = token_index(g, s);
        float4 v = *(const float4*)(x + ((size_t)b * NTOK + n) * C_ + c4 * 4);
        __half2* dst = (__half2*)(Xs + s * LDH + c4 * 4);
        dst[0] = __floats2half2_rn(v.x, v.y);
        dst[1] = __floats2half2_rn(v.z, v.w);
    }
    CP_WAIT0();
    __syncthreads();                          // X + W0 ready

    const uint32_t xfrag0 = xb + (((mrow + a_row) * LDH) + a_k8) * 2;
    const uint32_t xfrag1 = xfrag0 + 16 * LDH * 2;

    // ---- QKV: 3 full-width chunks. Q -> registers; K,V -> smem ----
    uint32_t qa[2][2][4];                     // [m-subtile][kt][regs]

    #pragma unroll
    for (int ch = 0; ch < 3; ch++) {
        float c[2][4][4];
        #pragma unroll
        for (int mi = 0; mi < 2; mi++)
            #pragma unroll
            for (int nj = 0; nj < 4; nj++)
                #pragma unroll
                for (int q = 0; q < 4; q++) c[mi][nj][q] = 0.f;

        #pragma unroll
        for (int kt = 0; kt < 8; kt++) {
            uint32_t a0[4], a1[4];
            ldmx4(a0, xfrag0 + kt * 32);
            ldmx4(a1, xfrag1 + kt * 32);
            #pragma unroll
            for (int np = 0; np < 2; np++) {
                uint32_t bb[4];
                ldmx4(bb, wb + (((ncol + np * 16 + b_row) * LDH) +
                                kt * 16 + b_k8) * 2);
                mma_f16(c[0][np * 2], a0, bb);
                mma_f16(c[0][np * 2 + 1], a0, bb + 2);
                mma_f16(c[1][np * 2], a1, bb);
                mma_f16(c[1][np * 2 + 1], a1, bb + 2);
            }
        }

        if (ch == 0) {
            // Q: repack C-fragments into mma A-fragments (head = wid>>1)
            #pragma unroll
            for (int mi = 0; mi < 2; mi++)
                #pragma unroll
                for (int kt = 0; kt < 2; kt++) {
                    qa[mi][kt][0] = h2u(__floats2half2_rn(c[mi][2 * kt][0],
                                                          c[mi][2 * kt][1]));
                    qa[mi][kt][1] = h2u(__floats2half2_rn(c[mi][2 * kt][2],
                                                          c[mi][2 * kt][3]));
                    qa[mi][kt][2] = h2u(__floats2half2_rn(c[mi][2 * kt + 1][0],
                                                          c[mi][2 * kt + 1][1]));
                    qa[mi][kt][3] = h2u(__floats2half2_rn(c[mi][2 * kt + 1][2],
                                                          c[mi][2 * kt + 1][3]));
                }
        } else {
            __half* T = (ch == 1) ? Kh : Vh;  // K-major [64][LDH]
            #pragma unroll
            for (int mi = 0; mi < 2; mi++)
                #pragma unroll
                for (int nj = 0; nj < 4; nj++) {
                    int r = mrow + mi * 16 + lr;
                    int col = ncol + nj * 8 + 2 * lc;
                    *(__half2*)(T + r * LDH + col) =
                        __floats2half2_rn(c[mi][nj][0], c[mi][nj][1]);
                    *(__half2*)(T + (r + 8) * LDH + col) =
                        __floats2half2_rn(c[mi][nj][2], c[mi][nj][3]);
                }
        }
        __syncthreads();                      // mma reads + epilogue done

        if (ch < 2) {
            const __half* src = g_wq_h + (size_t)(ch + 1) * 128 * C_;
            #pragma unroll
            for (int it = 0; it < 8; it++) {
                int r = wr + it * 16;
                cp16(wb + (r * LDH + wc8) * 2, src + (size_t)r * C_ + wc8);
            }
            CP_COMMIT();
            CP_WAIT0();
            __syncthreads();                  // next W ready
        }
    }

    // ---- prefetch full Wp (overlaps the attention phase) ----
    #pragma unroll
    for (int it = 0; it < 8; it++) {
        int r = wr + it * 16;
        cp16(wb + (r * LDH + wc8) * 2, g_wp_h + (size_t)r * C_ + wc8);
    }
    CP_COMMIT();

    // ---- attention: 32 rows x head per warp, single pass ----
    // S = Q K^T : sf[mi][nj], K fragments shared across both m-subtiles
    float sf[2][8][4];
    #pragma unroll
    for (int mi = 0; mi < 2; mi++)
        #pragma unroll
        for (int nj = 0; nj < 8; nj++)
            #pragma unroll
            for (int q = 0; q < 4; q++) sf[mi][nj][q] = 0.f;

    #pragma unroll
    for (int kt = 0; kt < 2; kt++) {
        #pragma unroll
        for (int np = 0; np < 4; np++) {
            uint32_t bb[4];
            ldmx4(bb, kb + (((np * 16 + b_row) * LDH) +
                            hcol + kt * 16 + b_k8) * 2);
            mma_f16(sf[0][np * 2], qa[0][kt], bb);
            mma_f16(sf[0][np * 2 + 1], qa[0][kt], bb + 2);
            mma_f16(sf[1][np * 2], qa[1][kt], bb);
            mma_f16(sf[1][np * 2 + 1], qa[1][kt], bb + 2);
        }
    }

    // softmax per m-subtile (rows lr -> c0c1, lr+8 -> c2c3)
    float invlo[2], invhi[2];
    uint32_t ph[2][8][2];
    #pragma unroll
    for (int mi = 0; mi < 2; mi++) {
        float mlo = -1e30f, mhi = -1e30f;
        #pragma unroll
        for (int nj = 0; nj < 8; nj++) {
            mlo = fmaxf(mlo, fmaxf(sf[mi][nj][0], sf[mi][nj][1]));
            mhi = fmaxf(mhi, fmaxf(sf[mi][nj][2], sf[mi][nj][3]));
        }
        mlo = fmaxf(mlo, __shfl_xor_sync(0xffffffffu, mlo, 1));
        mlo = fmaxf(mlo, __shfl_xor_sync(0xffffffffu, mlo, 2));
        mhi = fmaxf(mhi, __shfl_xor_sync(0xffffffffu, mhi, 1));
        mhi = fmaxf(mhi, __shfl_xor_sync(0xffffffffu, mhi, 2));

        float slo = 0.f, shi = 0.f;
        #pragma unroll
        for (int nj = 0; nj < 8; nj++) {
            float e0 = __expf((sf[mi][nj][0] - mlo) * SCALE);
            float e1 = __expf((sf[mi][nj][1] - mlo) * SCALE);
            float e2 = __expf((sf[mi][nj][2] - mhi) * SCALE);
            float e3 = __expf((sf[mi][nj][3] - mhi) * SCALE);
            slo += e0 + e1;
            shi += e2 + e3;
            ph[mi][nj][0] = h2u(__floats2half2_rn(e0, e1));
            ph[mi][nj][1] = h2u(__floats2half2_rn(e2, e3));
        }
        slo += __shfl_xor_sync(0xffffffffu, slo, 1);
        slo += __shfl_xor_sync(0xffffffffu, slo, 2);
        shi += __shfl_xor_sync(0xffffffffu, shi, 1);
        shi += __shfl_xor_sync(0xffffffffu, shi, 2);
        invlo[mi] = 1.f / slo;
        invhi[mi] = 1.f / shi;
    }

    // O = P V: V fragments shared across both m-subtiles
    float o[2][4][4];
    #pragma unroll
    for (int mi = 0; mi < 2; mi++)
        #pragma unroll
        for (int nj = 0; nj < 4; nj++)
            #pragma unroll
            for (int q = 0; q < 4; q++) o[mi][nj][q] = 0.f;

    #pragma unroll
    for (int kt = 0; kt < 4; kt++) {
        uint32_t a[2][4];
        #pragma unroll
        for (int mi = 0; mi < 2; mi++) {
            a[mi][0] = ph[mi][2 * kt][0];
            a[mi][1] = ph[mi][2 * kt][1];
            a[mi][2] = ph[mi][2 * kt + 1][0];
            a[mi][3] = ph[mi][2 * kt + 1][1];
        }
        #pragma unroll
        for (int np = 0; np < 2; np++) {
            uint32_t bb[4];
            ldmx4t(bb, vb + (((kt * 16 + v_row) * LDH) +
                             hcol + np * 16 + v_c8) * 2);
            mma_f16(o[0][np * 2], a[0], bb);
            mma_f16(o[0][np * 2 + 1], a[0], bb + 2);
            mma_f16(o[1][np * 2], a[1], bb);
            mma_f16(o[1][np * 2 + 1], a[1], bb + 2);
        }
    }

    // normalize + store O into Xs (this warp's 32 rows, head's 32 cols)
    __half* Oh = Xs;
    #pragma unroll
    for (int mi = 0; mi < 2; mi++) {
        int r = mrow + mi * 16 + lr;
        #pragma unroll
        for (int nj = 0; nj < 4; nj++) {
            int col = hcol + nj * 8 + 2 * lc;
            *(__half2*)(Oh + r * LDH + col) =
                __floats2half2_rn(o[mi][nj][0] * invlo[mi],
                                  o[mi][nj][1] * invlo[mi]);
            *(__half2*)(Oh + (r + 8) * LDH + col) =
                __floats2half2_rn(o[mi][nj][2] * invhi[mi],
                                  o[mi][nj][3] * invhi[mi]);
        }
    }
    CP_WAIT0();
    __syncthreads();                          // O complete; Wp ready

    // ---- proj: single pass, out = O * Wp^T + bias ----
    {
        float c[2][4][4];
        #pragma unroll
        for (int mi = 0; mi < 2; mi++)
            #pragma unroll
            for (int nj = 0; nj < 4; nj++)
                #pragma unroll
                for (int q = 0; q < 4; q++) c[mi][nj][q] = 0.f;

        #pragma unroll
        for (int kt = 0; kt < 8; kt++) {
            uint32_t a0[4], a1[4];
            ldmx4(a0, xfrag0 + kt * 32);      // O fragments
            ldmx4(a1, xfrag1 + kt * 32);
            #pragma unroll
            for (int np = 0; np < 2; np++) {
                uint32_t bb[4];
                ldmx4(bb, wb + (((ncol + np * 16 + b_row) * LDH) +
                                kt * 16 + b_k8) * 2);
                mma_f16(c[0][np * 2], a0, bb);
                mma_f16(c[0][np * 2 + 1], a0, bb + 2);
                mma_f16(c[1][np * 2], a1, bb);
                mma_f16(c[1][np * 2 + 1], a1, bb + 2);
            }
        }

        #pragma unroll
        for (int mi = 0; mi < 2; mi++) {
            int r = mrow + mi * 16 + lr;
            int n0t = token_index(g, r);
            int n1t = token_index(g, r + 8);
            float* r0 = out + ((size_t)b * NTOK + n0t) * C_;
            float* r1 = out + ((size_t)b * NTOK + n1t) * C_;
            #pragma unroll
            for (int nj = 0; nj < 4; nj++) {
                int col = ncol + nj * 8 + 2 * lc;
                float bx = bp[col], by = bp[col + 1];
                *(float2*)(r0 + col) = make_float2(c[mi][nj][0] + bx,
                                                   c[mi][nj][1] + by);
                *(float2*)(r1 + col) = make_float2(c[mi][nj][2] + bx,
                                                   c[mi][nj][3] + by);
            }
        }
    }
}

// ---------------------------------------------------------------------------
extern "C" void kernel_launch(void* const* d_in, const int* in_sizes, int n_in,
                              void* d_out, int out_size) {
    (void)in_sizes; (void)n_in; (void)out_size;
    const float* x      = (const float*)d_in[0];
    const float* w_qkv  = (const float*)d_in[1];
    const float* w_proj = (const float*)d_in[2];
    const float* b_proj = (const float*)d_in[3];
    float* out = (float*)d_out;

    cudaFuncSetAttribute(fused_all,
                         cudaFuncAttributeMaxDynamicSharedMemorySize, SMEM_FUSED);

    cvt_weights<<<64, 256>>>(w_qkv, w_proj);
    fused_all<<<B_ * G_, 256, SMEM_FUSED>>>(x, b_proj, out);
}

// round 13
// speedup vs baseline: 2.3290x; 1.0577x over previous
#include <cuda_runtime.h>
#include <cuda_fp16.h>
#include <cstdint>

// ---------------------------------------------------------------------------
// GroupAttention (Swin window attention)
// B=32, N=4096 (64x64), C=128, WS=8 -> G=64 windows, S=64 tokens/window
// heads=4, hd=32.
// Round 13: hide all W loads behind compute. W ping-pongs between Ws and the
// (dead-until-epilogue) K/V region: W0 under X-load, W1 under Q GEMM,
// W2 under K GEMM (K result deferred in regs), Wp under attention.
// 5 barriers total. Q in registers, 32x32 warp tiles, 2 CTAs/SM.
// ---------------------------------------------------------------------------

#define B_    32
#define NTOK  4096
#define C_    128
#define G_    64
#define S_    64

__device__ __half g_wq_h[384 * 128];
__device__ __half g_wp_h[128 * 128];

__device__ __forceinline__ int token_index(int g, int s) {
    return ((g >> 3) << 9) + ((s >> 3) << 6) + ((g & 7) << 3) + (s & 7);
}

__device__ __forceinline__ uint32_t h2u(__half2 h) { return *(uint32_t*)&h; }

__device__ __forceinline__ uint32_t smem_u32(const void* p) {
    uint32_t a;
    asm("{ .reg .u64 t; cvta.to.shared.u64 t, %1; cvt.u32.u64 %0, t; }"
        : "=r"(a) : "l"(p));
    return a;
}

__device__ __forceinline__ void mma_f16(float* c, const uint32_t* a,
                                        const uint32_t* b) {
    asm volatile(
        "mma.sync.aligned.m16n8k16.row.col.f32.f16.f16.f32 "
        "{%0,%1,%2,%3}, {%4,%5,%6,%7}, {%8,%9}, {%0,%1,%2,%3};"
        : "+f"(c[0]), "+f"(c[1]), "+f"(c[2]), "+f"(c[3])
        : "r"(a[0]), "r"(a[1]), "r"(a[2]), "r"(a[3]), "r"(b[0]), "r"(b[1]));
}

__device__ __forceinline__ void ldmx4(uint32_t* r, uint32_t addr) {
    asm volatile(
        "ldmatrix.sync.aligned.m8n8.x4.shared.b16 {%0,%1,%2,%3}, [%4];"
        : "=r"(r[0]), "=r"(r[1]), "=r"(r[2]), "=r"(r[3]) : "r"(addr));
}

__device__ __forceinline__ void ldmx4t(uint32_t* r, uint32_t addr) {
    asm volatile(
        "ldmatrix.sync.aligned.m8n8.x4.trans.shared.b16 {%0,%1,%2,%3}, [%4];"
        : "=r"(r[0]), "=r"(r[1]), "=r"(r[2]), "=r"(r[3]) : "r"(addr));
}

__device__ __forceinline__ void cp16(uint32_t dst, const void* src) {
    asm volatile("cp.async.cg.shared.global [%0], [%1], 16;"
                 :: "r"(dst), "l"(src));
}
#define CP_COMMIT() asm volatile("cp.async.commit_group;" ::: "memory")
#define CP_WAIT0()  asm volatile("cp.async.wait_group 0;" ::: "memory")

// row stride in halfwords: 68 words % 32 == 4 -> conflict-free ldmatrix
#define LDH 136

#define OFF_X  0                        // Xs/Oh  [64][136] : 17408
#define OFF_W  17408                    // Ws    [128][136] : 34816
#define OFF_K  52224                    // Kh     [64][136] : 17408  }  also the
#define OFF_V  69632                    // Vh     [64][136] : 17408  }  W1 buffer
#define SMEM_FUSED 87040                // x2 CTAs = 174KB/SM

#define SCALE 0.17677669529663687f

// ---------------------------------------------------------------------------
__global__ void __launch_bounds__(256) cvt_weights(const float* __restrict__ wq,
                                                   const float* __restrict__ wp) {
    int idx = blockIdx.x * 256 + threadIdx.x;    // 16384 float4 slots
    if (idx < 12288) {
        float4 v = ((const float4*)wq)[idx];
        __half2* d = (__half2*)g_wq_h + idx * 2;
        d[0] = __floats2half2_rn(v.x, v.y);
        d[1] = __floats2half2_rn(v.z, v.w);
    } else {
        int j = idx - 12288;
        float4 v = ((const float4*)wp)[j];
        __half2* d = (__half2*)g_wp_h + j * 2;
        d[0] = __floats2half2_rn(v.x, v.y);
        d[1] = __floats2half2_rn(v.z, v.w);
    }
}

// 32x32 warp tile x K=128 GEMM: A fragments from Xs, B rows from wbase.
__device__ __forceinline__ void gemm128(uint32_t xfrag0, uint32_t xfrag1,
                                        uint32_t wbase, int ncol,
                                        int b_row, int b_k8,
                                        float c[2][4][4]) {
    #pragma unroll
    for (int mi = 0; mi < 2; mi++)
        #pragma unroll
        for (int nj = 0; nj < 4; nj++)
            #pragma unroll
            for (int q = 0; q < 4; q++) c[mi][nj][q] = 0.f;

    #pragma unroll
    for (int kt = 0; kt < 8; kt++) {
        uint32_t a0[4], a1[4];
        ldmx4(a0, xfrag0 + kt * 32);
        ldmx4(a1, xfrag1 + kt * 32);
        #pragma unroll
        for (int np = 0; np < 2; np++) {
            uint32_t bb[4];
            ldmx4(bb, wbase + (((ncol + np * 16 + b_row) * LDH) +
                               kt * 16 + b_k8) * 2);
            mma_f16(c[0][np * 2], a0, bb);
            mma_f16(c[0][np * 2 + 1], a0, bb + 2);
            mma_f16(c[1][np * 2], a1, bb);
            mma_f16(c[1][np * 2 + 1], a1, bb + 2);
        }
    }
}

// ---------------------------------------------------------------------------
// Fused kernel: one block per window, 256 threads (8 warps), 2 CTAs/SM.
// Warp w: GEMM tile rows (w&1)*32 x cols (w>>1)*32; attention rows = tile
// rows, head = w>>1 (Q fragments stay in registers).
// ---------------------------------------------------------------------------
__global__ void __launch_bounds__(256, 2)
fused_all(const float* __restrict__ x, const float* __restrict__ bp,
          float* __restrict__ out) {
    extern __shared__ char sm[];
    __half* Xs = (__half*)(sm + OFF_X);       // X, then O
    __half* Ws = (__half*)(sm + OFF_W);
    __half* Kh = (__half*)(sm + OFF_K);
    __half* Vh = (__half*)(sm + OFF_V);

    const uint32_t xb = smem_u32(Xs);
    const uint32_t wb = smem_u32(Ws);
    const uint32_t kb = smem_u32(Kh);         // also base of the W1 buffer
    const uint32_t vb = smem_u32(Vh);

    const int tid = threadIdx.x;
    const int wid = tid >> 5, lane = tid & 31;
    const int lr = lane >> 2, lc = lane & 3;
    const int bg = blockIdx.x;
    const int b = bg >> 6, g = bg & 63;

    const int mrow = (wid & 1) * 32;
    const int ncol = (wid >> 1) * 32;
    const int hcol = ncol;

    // ldmatrix lane address components
    const int a_row = lane & 15;
    const int a_k8  = (lane >> 4) << 3;
    const int b_row = ((lane >> 4) << 3) + (lane & 7);
    const int b_k8  = ((lane >> 3) & 1) << 3;
    const int v_row = (lane & 7) + (((lane >> 3) & 1) << 3);
    const int v_c8  = (lane >> 4) << 3;

    // W fill via cp.async: 128 rows x 16 chunks(16B), 8 chunks/thread
    const int wr  = tid >> 4;
    const int wc8 = (tid & 15) * 8;

    // ---- phase 0: W0 -> Ws under the X gather ----
    #pragma unroll
    for (int it = 0; it < 8; it++) {
        int r = wr + it * 16;
        cp16(wb + (r * LDH + wc8) * 2, g_wq_h + (size_t)r * C_ + wc8);
    }
    CP_COMMIT();

    #pragma unroll
    for (int it = 0; it < 8; it++) {
        int fidx = tid + it * 256;            // 2048 float4s: 64 rows x 32
        int s = fidx >> 5;
        int c4 = fidx & 31;
        int n = token_index(g, s);
        float4 v = *(const float4*)(x + ((size_t)b * NTOK + n) * C_ + c4 * 4);
        __half2* dst = (__half2*)(Xs + s * LDH + c4 * 4);
        dst[0] = __floats2half2_rn(v.x, v.y);
        dst[1] = __floats2half2_rn(v.z, v.w);
    }
    CP_WAIT0();
    __syncthreads();                          // (1) X + W0 ready

    const uint32_t xfrag0 = xb + (((mrow + a_row) * LDH) + a_k8) * 2;
    const uint32_t xfrag1 = xfrag0 + 16 * LDH * 2;

    // ---- ch0 (Q): W1 -> [Kh:Vh] region under the Q GEMM ----
    #pragma unroll
    for (int it = 0; it < 8; it++) {
        int r = wr + it * 16;
        cp16(kb + (r * LDH + wc8) * 2, g_wq_h + (size_t)(128 + r) * C_ + wc8);
    }
    CP_COMMIT();

    uint32_t qa[2][2][4];
    {
        float cq[2][4][4];
        gemm128(xfrag0, xfrag1, wb, ncol, b_row, b_k8, cq);
        // fold softmax scale into Q, repack C-frags -> A-frags
        #pragma unroll
        for (int mi = 0; mi < 2; mi++)
            #pragma unroll
            for (int kt = 0; kt < 2; kt++) {
                qa[mi][kt][0] = h2u(__floats2half2_rn(cq[mi][2 * kt][0] * SCALE,
                                                      cq[mi][2 * kt][1] * SCALE));
                qa[mi][kt][1] = h2u(__floats2half2_rn(cq[mi][2 * kt][2] * SCALE,
                                                      cq[mi][2 * kt][3] * SCALE));
                qa[mi][kt][2] = h2u(__floats2half2_rn(cq[mi][2 * kt + 1][0] * SCALE,
                                                      cq[mi][2 * kt + 1][1] * SCALE));
                qa[mi][kt][3] = h2u(__floats2half2_rn(cq[mi][2 * kt + 1][2] * SCALE,
                                                      cq[mi][2 * kt + 1][3] * SCALE));
            }
    }
    CP_WAIT0();
    __syncthreads();                          // (2) ch0 Ws reads done; W1 ready

    // ---- ch1 (K): W2 -> Ws under the K GEMM; K result deferred in regs ----
    #pragma unroll
    for (int it = 0; it < 8; it++) {
        int r = wr + it * 16;
        cp16(wb + (r * LDH + wc8) * 2, g_wq_h + (size_t)(256 + r) * C_ + wc8);
    }
    CP_COMMIT();

    float ck[2][4][4];
    gemm128(xfrag0, xfrag1, kb, ncol, b_row, b_k8, ck);   // reads W1
    CP_WAIT0();
    __syncthreads();                          // (3) W1 reads done; W2 ready

    // write deferred K into Kh (over dead W1 rows 0..63)
    #pragma unroll
    for (int mi = 0; mi < 2; mi++)
        #pragma unroll
        for (int nj = 0; nj < 4; nj++) {
            int r = mrow + mi * 16 + lr;
            int col = ncol + nj * 8 + 2 * lc;
            *(__half2*)(Kh + r * LDH + col) =
                __floats2half2_rn(ck[mi][nj][0], ck[mi][nj][1]);
            *(__half2*)(Kh + (r + 8) * LDH + col) =
                __floats2half2_rn(ck[mi][nj][2], ck[mi][nj][3]);
        }

    // ---- ch2 (V): compute from Ws; epilogue -> Vh (dead W1 rows 64..127) ----
    {
        float cv[2][4][4];
        gemm128(xfrag0, xfrag1, wb, ncol, b_row, b_k8, cv);
        #pragma unroll
        for (int mi = 0; mi < 2; mi++)
            #pragma unroll
            for (int nj = 0; nj < 4; nj++) {
                int r = mrow + mi * 16 + lr;
                int col = ncol + nj * 8 + 2 * lc;
                *(__half2*)(Vh + r * LDH + col) =
                    __floats2half2_rn(cv[mi][nj][0], cv[mi][nj][1]);
                *(__half2*)(Vh + (r + 8) * LDH + col) =
                    __floats2half2_rn(cv[mi][nj][2], cv[mi][nj][3]);
            }
    }
    __syncthreads();                          // (4) K,V ready; ch2 Ws reads done

    // ---- Wp -> Ws under the attention phase ----
    #pragma unroll
    for (int it = 0; it < 8; it++) {
        int r = wr + it * 16;
        cp16(wb + (r * LDH + wc8) * 2, g_wp_h + (size_t)r * C_ + wc8);
    }
    CP_COMMIT();

    // ---- attention: 32 rows x head per warp, single pass ----
    float sf[2][8][4];
    #pragma unroll
    for (int mi = 0; mi < 2; mi++)
        #pragma unroll
        for (int nj = 0; nj < 8; nj++)
            #pragma unroll
            for (int q = 0; q < 4; q++) sf[mi][nj][q] = 0.f;

    #pragma unroll
    for (int kt = 0; kt < 2; kt++) {
        #pragma unroll
        for (int np = 0; np < 4; np++) {
            uint32_t bb[4];
            ldmx4(bb, kb + (((np * 16 + b_row) * LDH) +
                            hcol + kt * 16 + b_k8) * 2);
            mma_f16(sf[0][np * 2], qa[0][kt], bb);
            mma_f16(sf[0][np * 2 + 1], qa[0][kt], bb + 2);
            mma_f16(sf[1][np * 2], qa[1][kt], bb);
            mma_f16(sf[1][np * 2 + 1], qa[1][kt], bb + 2);
        }
    }

    // softmax per m-subtile (scores already scaled via Q)
    float invlo[2], invhi[2];
    uint32_t ph[2][8][2];
    #pragma unroll
    for (int mi = 0; mi < 2; mi++) {
        float mlo = -1e30f, mhi = -1e30f;
        #pragma unroll
        for (int nj = 0; nj < 8; nj++) {
            mlo = fmaxf(mlo, fmaxf(sf[mi][nj][0], sf[mi][nj][1]));
            mhi = fmaxf(mhi, fmaxf(sf[mi][nj][2], sf[mi][nj][3]));
        }
        mlo = fmaxf(mlo, __shfl_xor_sync(0xffffffffu, mlo, 1));
        mlo = fmaxf(mlo, __shfl_xor_sync(0xffffffffu, mlo, 2));
        mhi = fmaxf(mhi, __shfl_xor_sync(0xffffffffu, mhi, 1));
        mhi = fmaxf(mhi, __shfl_xor_sync(0xffffffffu, mhi, 2));

        float slo = 0.f, shi = 0.f;
        #pragma unroll
        for (int nj = 0; nj < 8; nj++) {
            float e0 = __expf(sf[mi][nj][0] - mlo);
            float e1 = __expf(sf[mi][nj][1] - mlo);
            float e2 = __expf(sf[mi][nj][2] - mhi);
            float e3 = __expf(sf[mi][nj][3] - mhi);
            slo += e0 + e1;
            shi += e2 + e3;
            ph[mi][nj][0] = h2u(__floats2half2_rn(e0, e1));
            ph[mi][nj][1] = h2u(__floats2half2_rn(e2, e3));
        }
        slo += __shfl_xor_sync(0xffffffffu, slo, 1);
        slo += __shfl_xor_sync(0xffffffffu, slo, 2);
        shi += __shfl_xor_sync(0xffffffffu, shi, 1);
        shi += __shfl_xor_sync(0xffffffffu, shi, 2);
        invlo[mi] = 1.f / slo;
        invhi[mi] = 1.f / shi;
    }

    // O = P V
    float o[2][4][4];
    #pragma unroll
    for (int mi = 0; mi < 2; mi++)
        #pragma unroll
        for (int nj = 0; nj < 4; nj++)
            #pragma unroll
            for (int q = 0; q < 4; q++) o[mi][nj][q] = 0.f;

    #pragma unroll
    for (int kt = 0; kt < 4; kt++) {
        uint32_t a[2][4];
        #pragma unroll
        for (int mi = 0; mi < 2; mi++) {
            a[mi][0] = ph[mi][2 * kt][0];
            a[mi][1] = ph[mi][2 * kt][1];
            a[mi][2] = ph[mi][2 * kt + 1][0];
            a[mi][3] = ph[mi][2 * kt + 1][1];
        }
        #pragma unroll
        for (int np = 0; np < 2; np++) {
            uint32_t bb[4];
            ldmx4t(bb, vb + (((kt * 16 + v_row) * LDH) +
                             hcol + np * 16 + v_c8) * 2);
            mma_f16(o[0][np * 2], a[0], bb);
            mma_f16(o[0][np * 2 + 1], a[0], bb + 2);
            mma_f16(o[1][np * 2], a[1], bb);
            mma_f16(o[1][np * 2 + 1], a[1], bb + 2);
        }
    }

    // normalize + store O into Xs
    __half* Oh = Xs;
    #pragma unroll
    for (int mi = 0; mi < 2; mi++) {
        int r = mrow + mi * 16 + lr;
        #pragma unroll
        for (int nj = 0; nj < 4; nj++) {
            int col = hcol + nj * 8 + 2 * lc;
            *(__half2*)(Oh + r * LDH + col) =
                __floats2half2_rn(o[mi][nj][0] * invlo[mi],
                                  o[mi][nj][1] * invlo[mi]);
            *(__half2*)(Oh + (r + 8) * LDH + col) =
                __floats2half2_rn(o[mi][nj][2] * invhi[mi],
                                  o[mi][nj][3] * invhi[mi]);
        }
    }
    CP_WAIT0();
    __syncthreads();                          // (5) O complete; Wp ready

    // ---- proj: single pass, out = O * Wp^T + bias ----
    {
        float c[2][4][4];
        gemm128(xfrag0, xfrag1, wb, ncol, b_row, b_k8, c);

        #pragma unroll
        for (int mi = 0; mi < 2; mi++) {
            int r = mrow + mi * 16 + lr;
            int n0t = token_index(g, r);
            int n1t = token_index(g, r + 8);
            float* r0 = out + ((size_t)b * NTOK + n0t) * C_;
            float* r1 = out + ((size_t)b * NTOK + n1t) * C_;
            #pragma unroll
            for (int nj = 0; nj < 4; nj++) {
                int col = ncol + nj * 8 + 2 * lc;
                float bx = bp[col], by = bp[col + 1];
                *(float2*)(r0 + col) = make_float2(c[mi][nj][0] + bx,
                                                   c[mi][nj][1] + by);
                *(float2*)(r1 + col) = make_float2(c[mi][nj][2] + bx,
                                                   c[mi][nj][3] + by);
            }
        }
    }
}

// ---------------------------------------------------------------------------
extern "C" void kernel_launch(void* const* d_in, const int* in_sizes, int n_in,
                              void* d_out, int out_size) {
    (void)in_sizes; (void)n_in; (void)out_size;
    const float* x      = (const float*)d_in[0];
    const float* w_qkv  = (const float*)d_in[1];
    const float* w_proj = (const float*)d_in[2];
    const float* b_proj = (const float*)d_in[3];
    float* out = (float*)d_out;

    cudaFuncSetAttribute(fused_all,
                         cudaFuncAttributeMaxDynamicSharedMemorySize, SMEM_FUSED);

    cvt_weights<<<64, 256>>>(w_qkv, w_proj);
    fused_all<<<B_ * G_, 256, SMEM_FUSED>>>(x, b_proj, out);
}